// round 1
// baseline (speedup 1.0000x reference)
#include <cuda_runtime.h>
#include <math.h>

#define NN 100000
#define EE 800000
#define NB_MAX 512

// ---------------- scratch (device globals; no cudaMalloc allowed) ----------------
__device__ int   g_cnt[NN];
__device__ int   g_row[NN + 1];
__device__ int   g_cur[NN];
__device__ int   g_bsum[NB_MAX];
__device__ int   g_csrc[EE];
__device__ float g_h [NN * 128];
__device__ float g_xl[NN * 128];
__device__ float g_xr[NN * 128];
__device__ float g_gg[NN * 128];
__device__ float g_w1cat[128 * 128];
__device__ float g_b1cat[128];

// ---------------- CSR build ----------------
__global__ void k_zero(int n) {
    int i = blockIdx.x * blockDim.x + threadIdx.x;
    if (i < n) g_cnt[i] = 0;
}

__global__ void k_count(const int* __restrict__ dstv, int e) {
    int i = blockIdx.x * blockDim.x + threadIdx.x;
    if (i < e) atomicAdd(&g_cnt[dstv[i]], 1);
}

__global__ void k_scan_a(int n) {
    __shared__ int sh[256];
    int i = blockIdx.x * 256 + threadIdx.x;
    int v = (i < n) ? g_cnt[i] : 0;
    sh[threadIdx.x] = v;
    __syncthreads();
    #pragma unroll
    for (int o = 1; o < 256; o <<= 1) {
        int t = (threadIdx.x >= o) ? sh[threadIdx.x - o] : 0;
        __syncthreads();
        sh[threadIdx.x] += t;
        __syncthreads();
    }
    if (i < n) g_row[i] = sh[threadIdx.x] - v;           // exclusive within block
    if (threadIdx.x == 255) g_bsum[blockIdx.x] = sh[255];
}

__global__ void k_scan_b(int nb) {
    __shared__ int sh[NB_MAX];
    int t = threadIdx.x;
    int v = (t < nb) ? g_bsum[t] : 0;
    sh[t] = v;
    __syncthreads();
    #pragma unroll
    for (int o = 1; o < NB_MAX; o <<= 1) {
        int u = (t >= o) ? sh[t - o] : 0;
        __syncthreads();
        sh[t] += u;
        __syncthreads();
    }
    if (t < nb) g_bsum[t] = sh[t] - v;                   // exclusive block offsets
}

__global__ void k_scan_c(int n, int e) {
    int i = blockIdx.x * 256 + threadIdx.x;
    if (i < n) {
        int r = g_row[i] + g_bsum[blockIdx.x];
        g_row[i] = r;
        g_cur[i] = r;
    }
    if (i == 0) g_row[n] = e;
}

__global__ void k_scatter(const int* __restrict__ srcv, const int* __restrict__ dstv, int e) {
    int i = blockIdx.x * blockDim.x + threadIdx.x;
    if (i < e) {
        int pos = atomicAdd(&g_cur[dstv[i]], 1);
        g_csrc[pos] = srcv[i];
    }
}

// Sort each node's adjacency list by src value -> deterministic summation order.
__global__ void k_sortcsr(int n) {
    int i = blockIdx.x * blockDim.x + threadIdx.x;
    if (i >= n) return;
    int b = g_row[i], e2 = g_row[i + 1];
    for (int a = b + 1; a < e2; a++) {
        int v = g_csrc[a];
        int k = a;
        while (k > b && g_csrc[k - 1] > v) { g_csrc[k] = g_csrc[k - 1]; k--; }
        g_csrc[k] = v;
    }
}

// ---------------- LayerNorm kernels ----------------
__global__ void __launch_bounds__(256) k_ln64(const float* __restrict__ x,
                                              const float* __restrict__ g,
                                              const float* __restrict__ b,
                                              float* __restrict__ out, int n) {
    int w = (blockIdx.x * 256 + threadIdx.x) >> 5;
    int lane = threadIdx.x & 31;
    if (w >= n) return;
    float2 v = *(const float2*)(x + (size_t)w * 64 + lane * 2);
    float s = v.x + v.y;
    float q = v.x * v.x + v.y * v.y;
    #pragma unroll
    for (int o = 16; o; o >>= 1) {
        s += __shfl_xor_sync(0xffffffffu, s, o);
        q += __shfl_xor_sync(0xffffffffu, q, o);
    }
    float m  = s * (1.f / 64.f);
    float var = q * (1.f / 64.f) - m * m;
    float rs = rsqrtf(var + 1e-5f);
    float2 gg = *(const float2*)(g + lane * 2);
    float2 bb = *(const float2*)(b + lane * 2);
    float2 o2;
    o2.x = (v.x - m) * rs * gg.x + bb.x;
    o2.y = (v.y - m) * rs * gg.y + bb.y;
    *(float2*)(out + (size_t)w * 64 + lane * 2) = o2;
}

__global__ void __launch_bounds__(256) k_ln128(const float* __restrict__ in,
                                               const float* __restrict__ g,
                                               const float* __restrict__ b,
                                               const float* __restrict__ res,
                                               float rscale, int doRelu,
                                               float* __restrict__ out, int n) {
    int w = (blockIdx.x * 256 + threadIdx.x) >> 5;
    int lane = threadIdx.x & 31;
    if (w >= n) return;
    int c0 = lane * 4;
    float4 v = *(const float4*)(in + (size_t)w * 128 + c0);
    float s = v.x + v.y + v.z + v.w;
    float q = v.x * v.x + v.y * v.y + v.z * v.z + v.w * v.w;
    #pragma unroll
    for (int o = 16; o; o >>= 1) {
        s += __shfl_xor_sync(0xffffffffu, s, o);
        q += __shfl_xor_sync(0xffffffffu, q, o);
    }
    float m   = s * (1.f / 128.f);
    float var = q * (1.f / 128.f) - m * m;
    float rs  = rsqrtf(var + 1e-5f);
    float4 gg = *(const float4*)(g + c0);
    float4 bb = *(const float4*)(b + c0);
    float4 y;
    y.x = (v.x - m) * rs * gg.x + bb.x;
    y.y = (v.y - m) * rs * gg.y + bb.y;
    y.z = (v.z - m) * rs * gg.z + bb.z;
    y.w = (v.w - m) * rs * gg.w + bb.w;
    if (res) {
        float4 r4 = *(const float4*)(res + (size_t)w * 128 + c0);
        y.x += rscale * r4.x; y.y += rscale * r4.y;
        y.z += rscale * r4.z; y.w += rscale * r4.w;
    }
    if (doRelu) {
        y.x = fmaxf(y.x, 0.f); y.y = fmaxf(y.y, 0.f);
        y.z = fmaxf(y.z, 0.f); y.w = fmaxf(y.w, 0.f);
    }
    *(float4*)(out + (size_t)w * 128 + c0) = y;
}

// ---------------- SGEMM: C[n,128] = A[n,K] * W[K,128] (+bias, relu) ----------------
template <int K>
__global__ void __launch_bounds__(256) k_gemm(const float* __restrict__ A,
                                              const float* __restrict__ W,
                                              float* __restrict__ C, int n,
                                              const float* __restrict__ bias, int doRelu) {
    __shared__ float Ws[32 * 128];
    __shared__ float As[32 * 64];
    const int tid  = threadIdx.x;
    const int row0 = blockIdx.x * 64;
    const int tm   = (tid >> 5) * 8;   // 8 rows per thread
    const int tc   = (tid & 31) * 4;   // 4 cols per thread
    float acc[8][4];
    #pragma unroll
    for (int r = 0; r < 8; r++)
        #pragma unroll
        for (int c = 0; c < 4; c++) acc[r][c] = 0.f;

    for (int k0 = 0; k0 < K; k0 += 32) {
        __syncthreads();
        // W chunk [32 x 128] linear copy
        #pragma unroll
        for (int i = tid * 4; i < 32 * 128; i += 1024)
            *(float4*)(Ws + i) = *(const float4*)(W + k0 * 128 + i);
        // A chunk [64 rows x 32 k], stored transposed As[k][m]
        #pragma unroll
        for (int it = 0; it < 2; it++) {
            int r  = (tid >> 3) + it * 32;
            int kk = (tid & 7) * 4;
            int grow = row0 + r;
            float4 a = make_float4(0.f, 0.f, 0.f, 0.f);
            if (grow < n) a = *(const float4*)(A + (size_t)grow * K + k0 + kk);
            As[(kk + 0) * 64 + r] = a.x;
            As[(kk + 1) * 64 + r] = a.y;
            As[(kk + 2) * 64 + r] = a.z;
            As[(kk + 3) * 64 + r] = a.w;
        }
        __syncthreads();
        #pragma unroll
        for (int k = 0; k < 32; k++) {
            float4 b  = *(const float4*)(Ws + k * 128 + tc);
            float4 a0 = *(const float4*)(As + k * 64 + tm);
            float4 a1 = *(const float4*)(As + k * 64 + tm + 4);
            float ar[8] = {a0.x, a0.y, a0.z, a0.w, a1.x, a1.y, a1.z, a1.w};
            #pragma unroll
            for (int r = 0; r < 8; r++) {
                acc[r][0] = fmaf(ar[r], b.x, acc[r][0]);
                acc[r][1] = fmaf(ar[r], b.y, acc[r][1]);
                acc[r][2] = fmaf(ar[r], b.z, acc[r][2]);
                acc[r][3] = fmaf(ar[r], b.w, acc[r][3]);
            }
        }
    }
    float4 bv = make_float4(0.f, 0.f, 0.f, 0.f);
    if (bias) bv = *(const float4*)(bias + tc);
    #pragma unroll
    for (int r = 0; r < 8; r++) {
        int grow = row0 + tm + r;
        if (grow < n) {
            float4 o;
            o.x = acc[r][0] + bv.x;
            o.y = acc[r][1] + bv.y;
            o.z = acc[r][2] + bv.z;
            o.w = acc[r][3] + bv.w;
            if (doRelu) {
                o.x = fmaxf(o.x, 0.f); o.y = fmaxf(o.y, 0.f);
                o.z = fmaxf(o.z, 0.f); o.w = fmaxf(o.w, 0.f);
            }
            *(float4*)(C + (size_t)grow * 128 + tc) = o;
        }
    }
}

// ---------------- GATv2 aggregation: warp per dst node, online softmax ----------------
// lane owns flat channels [4*lane, 4*lane+4); head of lane = lane/(32/H).
__global__ void __launch_bounds__(256) k_agg(const float* __restrict__ xl,
                                             const float* __restrict__ xr,
                                             const float* __restrict__ att,
                                             float* __restrict__ out, int n, int grp) {
    int w = (blockIdx.x * 256 + threadIdx.x) >> 5;
    int lane = threadIdx.x & 31;
    if (w >= n) return;
    int c0 = lane * 4;
    float4 a4 = *(const float4*)(att + c0);
    float4 r4 = *(const float4*)(xr + (size_t)w * 128 + c0);
    int beg = g_row[w], deg = g_row[w + 1] - beg;
    float m = -1e30f, s = 0.f;
    float4 acc = make_float4(0.f, 0.f, 0.f, 0.f);
    for (int j = -1; j < deg; j++) {       // j == -1 is the self-loop
        int sidx = (j < 0) ? w : g_csrc[beg + j];
        float4 x4 = *(const float4*)(xl + (size_t)sidx * 128 + c0);
        float e0 = x4.x + r4.x, e1 = x4.y + r4.y, e2 = x4.z + r4.z, e3 = x4.w + r4.w;
        e0 = (e0 > 0.f) ? e0 : 0.2f * e0;
        e1 = (e1 > 0.f) ? e1 : 0.2f * e1;
        e2 = (e2 > 0.f) ? e2 : 0.2f * e2;
        e3 = (e3 > 0.f) ? e3 : 0.2f * e3;
        float p = fmaf(a4.x, e0, fmaf(a4.y, e1, fmaf(a4.z, e2, a4.w * e3)));
        #pragma unroll
        for (int o = 1; o < 32; o <<= 1)
            if (o < grp) p += __shfl_xor_sync(0xffffffffu, p, o);
        float mn  = fmaxf(m, p);
        float sc  = __expf(m - mn);
        float wgt = __expf(p - mn);
        s = s * sc + wgt;
        acc.x = fmaf(acc.x, sc, wgt * x4.x);
        acc.y = fmaf(acc.y, sc, wgt * x4.y);
        acc.z = fmaf(acc.z, sc, wgt * x4.z);
        acc.w = fmaf(acc.w, sc, wgt * x4.w);
        m = mn;
    }
    float inv = 1.f / s;
    float4 o4 = make_float4(acc.x * inv, acc.y * inv, acc.z * inv, acc.w * inv);
    *(float4*)(out + (size_t)w * 128 + c0) = o4;
}

// ---------------- prediction heads ----------------
__global__ void k_w1cat(const float* __restrict__ w1a, const float* __restrict__ w1b,
                        const float* __restrict__ b1a, const float* __restrict__ b1b) {
    int i = blockIdx.x * blockDim.x + threadIdx.x;
    if (i < 128 * 64) {
        int r = i >> 6, c = i & 63;
        g_w1cat[r * 128 + c]      = w1a[i];
        g_w1cat[r * 128 + 64 + c] = w1b[i];
    }
    if (i < 64) { g_b1cat[i] = b1a[i]; g_b1cat[64 + i] = b1b[i]; }
}

__global__ void __launch_bounds__(256) k_head2(const float* __restrict__ T,
                                               const float* __restrict__ w2a,
                                               const float* __restrict__ b2a,
                                               const float* __restrict__ w2b,
                                               const float* __restrict__ b2b,
                                               float* __restrict__ out, int n) {
    int w = (blockIdx.x * 256 + threadIdx.x) >> 5;
    int lane = threadIdx.x & 31;
    if (w >= n) return;
    const float* t = T + (size_t)w * 128;
    float tA = fmaf(t[lane],      w2a[lane],      t[32 + lane] * w2a[32 + lane]);
    float tB = fmaf(t[64 + lane], w2b[lane],      t[96 + lane] * w2b[32 + lane]);
    #pragma unroll
    for (int o = 16; o; o >>= 1) {
        tA += __shfl_xor_sync(0xffffffffu, tA, o);
        tB += __shfl_xor_sync(0xffffffffu, tB, o);
    }
    if (lane == 0) {
        out[(size_t)2 * w]     = tA + b2a[0];
        out[(size_t)2 * w + 1] = tB + b2b[0];
    }
}

// ---------------- launch ----------------
extern "C" void kernel_launch(void* const* d_in, const int* in_sizes, int n_in,
                              void* d_out, int out_size) {
    const float* x       = (const float*)d_in[0];
    const int*   ei      = (const int*)  d_in[1];
    const float* ln_in_g = (const float*)d_in[2];
    const float* ln_in_b = (const float*)d_in[3];
    const float* w_l1    = (const float*)d_in[4];
    const float* w_r1    = (const float*)d_in[5];
    const float* att1    = (const float*)d_in[6];
    const float* ln1_g   = (const float*)d_in[7];
    const float* ln1_b   = (const float*)d_in[8];
    const float* w_l2    = (const float*)d_in[9];
    const float* w_r2    = (const float*)d_in[10];
    const float* att2    = (const float*)d_in[11];
    const float* ln2_g   = (const float*)d_in[12];
    const float* ln2_b   = (const float*)d_in[13];
    const float* w_l3    = (const float*)d_in[14];
    const float* w_r3    = (const float*)d_in[15];
    const float* att3    = (const float*)d_in[16];
    const float* ln3_g   = (const float*)d_in[17];
    const float* ln3_b   = (const float*)d_in[18];
    const float* rtt_w1  = (const float*)d_in[19];
    const float* rtt_b1  = (const float*)d_in[20];
    const float* rtt_w2  = (const float*)d_in[21];
    const float* rtt_b2  = (const float*)d_in[22];
    const float* ret_w1  = (const float*)d_in[23];
    const float* ret_b1  = (const float*)d_in[24];
    const float* ret_w2  = (const float*)d_in[25];
    const float* ret_b2  = (const float*)d_in[26];

    const int n = in_sizes[0] / 64;
    const int e = in_sizes[1] / 2;
    const int* srcv = ei;
    const int* dstv = ei + e;

    float *p_h, *p_xl, *p_xr, *p_gg, *p_w1, *p_b1;
    cudaGetSymbolAddress((void**)&p_h,  g_h);
    cudaGetSymbolAddress((void**)&p_xl, g_xl);
    cudaGetSymbolAddress((void**)&p_xr, g_xr);
    cudaGetSymbolAddress((void**)&p_gg, g_gg);
    cudaGetSymbolAddress((void**)&p_w1, g_w1cat);
    cudaGetSymbolAddress((void**)&p_b1, g_b1cat);

    const int NBn = (n + 255) / 256;
    const int EB  = (e + 255) / 256;
    const int WB  = (n + 7) / 8;      // warp-per-node, 256-thread blocks
    const int GB  = (n + 63) / 64;    // GEMM M-tiles

    // CSR build (shared by all three layers)
    k_zero   <<<NBn, 256>>>(n);
    k_count  <<<EB,  256>>>(dstv, e);
    k_scan_a <<<NBn, 256>>>(n);
    k_scan_b <<<1, NB_MAX>>>(NBn);
    k_scan_c <<<NBn, 256>>>(n, e);
    k_scatter<<<EB,  256>>>(srcv, dstv, e);
    k_sortcsr<<<NBn, 256>>>(n);
    k_w1cat  <<<32,  256>>>(rtt_w1, ret_w1, rtt_b1, ret_b1);

    // input LayerNorm: x -> g_gg as [n,64]
    k_ln64<<<WB, 256>>>(x, ln_in_g, ln_in_b, p_gg, n);

    // layer 0 (F_IN=64 -> 128, 4 heads, no residual)
    k_gemm<64><<<GB, 256>>>(p_gg, w_l1, p_xl, n, nullptr, 0);
    k_gemm<64><<<GB, 256>>>(p_gg, w_r1, p_xr, n, nullptr, 0);
    k_agg<<<WB, 256>>>(p_xl, p_xr, att1, p_gg, n, 8);
    k_ln128<<<WB, 256>>>(p_gg, ln1_g, ln1_b, nullptr, 0.f, 1, p_h, n);

    // layer 1 (128 -> 128, 4 heads, residual*0.1, relu)
    k_gemm<128><<<GB, 256>>>(p_h, w_l2, p_xl, n, nullptr, 0);
    k_gemm<128><<<GB, 256>>>(p_h, w_r2, p_xr, n, nullptr, 0);
    k_agg<<<WB, 256>>>(p_xl, p_xr, att2, p_gg, n, 8);
    k_ln128<<<WB, 256>>>(p_gg, ln2_g, ln2_b, p_h, 0.1f, 1, p_h, n);

    // layer 2 (128 -> 128, 1 head, residual*0.1, no relu)
    k_gemm<128><<<GB, 256>>>(p_h, w_l3, p_xl, n, nullptr, 0);
    k_gemm<128><<<GB, 256>>>(p_h, w_r3, p_xr, n, nullptr, 0);
    k_agg<<<WB, 256>>>(p_xl, p_xr, att3, p_gg, n, 32);
    k_ln128<<<WB, 256>>>(p_gg, ln3_g, ln3_b, p_h, 0.1f, 0, p_h, n);

    // prediction heads: T = relu(h @ [rtt_w1|ret_w1] + b) ; out = [T_a@w2a+b2a, T_b@w2b+b2b]
    k_gemm<128><<<GB, 256>>>(p_h, p_w1, p_xl, n, p_b1, 1);
    k_head2<<<WB, 256>>>(p_xl, rtt_w2, rtt_b2, ret_w2, ret_b2, (float*)d_out, n);
}